// round 4
// baseline (speedup 1.0000x reference)
#include <cuda_runtime.h>

#define NN 200000
#define NE 6400000
#define SCAN_B 512
#define NBLK ((NN + SCAN_B - 1) / SCAN_B)   // 391

// ---- scratch (device globals; no allocations allowed) ----
__device__ int   g_cnt[NN];        // in-degree (excl self-loop)
__device__ int   g_rowstart[NN];
__device__ int   g_cursor[NN];
__device__ int   g_bsum[NBLK];
__device__ int   g_boff[NBLK];
__device__ int   g_src32[NE];
__device__ int   g_dst32[NE];
__device__ int   g_csr[NE];        // src ids grouped by dst
__device__ float g_dinv[NN];
__device__ float g_h1[NN * 16];    // h1 * dinv[i]
__device__ float g_h2[NN * 8];     // h2 * dinv[i], padded to 8
__device__ int   g_is64;

// ---- fused: zero counts + dtype detection ----
__global__ void k_init(const unsigned int* w) {
    int i = blockIdx.x * blockDim.x + threadIdx.x;
    if (i < NN) g_cnt[i] = 0;
    if (i == 0) {
        int is64 = 1;
        #pragma unroll
        for (int k = 1; k < 32; k += 2)
            if (w[k] != 0u) is64 = 0;
        g_is64 = is64;
    }
}

// convert edge index to int32 + in-degree histogram (int atomics)
__global__ void k_convert_count(const void* __restrict__ ei) {
    int e = blockIdx.x * blockDim.x + threadIdx.x;
    if (e >= NE) return;
    int s, d;
    if (g_is64) {
        const long long* p = (const long long*)ei;
        s = (int)p[e];
        d = (int)p[(long long)NE + e];
    } else {
        const int* p = (const int*)ei;
        s = p[e];
        d = p[NE + e];
    }
    g_src32[e] = s;
    g_dst32[e] = d;
    atomicAdd(&g_cnt[d], 1);
}

// ---- exclusive prefix sum over g_cnt (3 kernels) ----
__global__ void k_scanA() {
    __shared__ int sh[SCAN_B];
    int i = blockIdx.x * SCAN_B + threadIdx.x;
    int v = (i < NN) ? g_cnt[i] : 0;
    sh[threadIdx.x] = v;
    __syncthreads();
    for (int off = 1; off < SCAN_B; off <<= 1) {
        int t = (threadIdx.x >= off) ? sh[threadIdx.x - off] : 0;
        __syncthreads();
        sh[threadIdx.x] += t;
        __syncthreads();
    }
    if (i < NN) g_rowstart[i] = sh[threadIdx.x] - v;
    if (threadIdx.x == SCAN_B - 1) g_bsum[blockIdx.x] = sh[threadIdx.x];
}

__global__ void k_scanB() {
    __shared__ int sh[SCAN_B];
    int v = (threadIdx.x < NBLK) ? g_bsum[threadIdx.x] : 0;
    sh[threadIdx.x] = v;
    __syncthreads();
    for (int off = 1; off < SCAN_B; off <<= 1) {
        int t = (threadIdx.x >= off) ? sh[threadIdx.x - off] : 0;
        __syncthreads();
        sh[threadIdx.x] += t;
        __syncthreads();
    }
    if (threadIdx.x < NBLK) g_boff[threadIdx.x] = sh[threadIdx.x] - v;
}

__global__ void k_scanC() {
    int i = blockIdx.x * blockDim.x + threadIdx.x;
    if (i >= NN) return;
    int r = g_rowstart[i] + g_boff[i / SCAN_B];
    g_rowstart[i] = r;
    g_cursor[i]   = r;
}

// counting-sort fill: csr[pos++] = src, grouped by dst
__global__ void k_fill() {
    int e = blockIdx.x * blockDim.x + threadIdx.x;
    if (e >= NE) return;
    int d = g_dst32[e];
    int pos = atomicAdd(&g_cursor[d], 1);
    g_csr[pos] = g_src32[e];
}

// dinv + layer-1 GEMM (x[21] @ W1[21x16]), x tiled through smem, pre-scaled by dinv
__global__ void k_layer1_node(const float* __restrict__ x, const float* __restrict__ W1) {
    __shared__ float sW[21 * 16];
    __shared__ float sX[256 * 21];
    for (int t = threadIdx.x; t < 21 * 16; t += blockDim.x) sW[t] = W1[t];
    int base = blockIdx.x * 256;
    {
        long long gbase = (long long)base * 21;
        int lim = (NN - base) * 21;
        if (lim > 256 * 21) lim = 256 * 21;
        for (int t = threadIdx.x; t < lim; t += blockDim.x)
            sX[t] = x[gbase + t];
    }
    __syncthreads();
    int i = base + threadIdx.x;
    if (i >= NN) return;
    float di = rsqrtf((float)g_cnt[i] + 1.0f);   // +1 self-loop
    g_dinv[i] = di;
    const float* xi = &sX[threadIdx.x * 21];
    float acc[16];
    #pragma unroll
    for (int f = 0; f < 16; f++) acc[f] = 0.0f;
    #pragma unroll
    for (int k = 0; k < 21; k++) {
        float xk = xi[k];
        #pragma unroll
        for (int f = 0; f < 16; f++) acc[f] = fmaf(xk, sW[k * 16 + f], acc[f]);
    }
    float4* h1p = (float4*)&g_h1[i * 16];
    #pragma unroll
    for (int q = 0; q < 4; q++) {
        float4 v;
        v.x = acc[q * 4 + 0] * di;
        v.y = acc[q * 4 + 1] * di;
        v.z = acc[q * 4 + 2] * di;
        v.w = acc[q * 4 + 3] * di;
        h1p[q] = v;
    }
}

// gather layer 1 + fused layer-2 node transform.
// warp per dst node; 32 csr entries loaded per outer iter (lane-per-edge),
// then 4 independent rounds of (shfl, float4 load) -> MLP=4.
// Epilogue: warp-reduce, shfl-broadcast agg1, relu+b1, @W2, *dinv -> g_h2.
__global__ void k_gather1(const float* __restrict__ b1, const float* __restrict__ W2) {
    __shared__ float sW[16 * 6];
    __shared__ float sb[16];
    if (threadIdx.x < 96) sW[threadIdx.x] = W2[threadIdx.x];
    if (threadIdx.x < 16) sb[threadIdx.x] = b1[threadIdx.x];
    __syncthreads();

    int i = blockIdx.x * 8 + (threadIdx.x >> 5);
    int lane = threadIdx.x & 31;
    int g = lane >> 2;   // edge sub-slot 0..7
    int q = lane & 3;    // feature quad 0..3
    int start = g_rowstart[i];
    int n = g_cnt[i];

    float4 acc;
    {   // self-loop: add once per quad (g==0 lanes only)
        float4 h = (g == 0) ? ((const float4*)&g_h1[i * 16])[q]
                            : make_float4(0.f, 0.f, 0.f, 0.f);
        acc = h;
    }
    for (int base = 0; base < n; base += 32) {
        int slot = base + lane;
        int v = (slot < n) ? g_csr[start + slot] : -1;
        #pragma unroll
        for (int r = 0; r < 4; r++) {
            int s = __shfl_sync(0xffffffffu, v, r * 8 + g);
            if (s >= 0) {
                float4 h = *(const float4*)&g_h1[s * 16 + q * 4];
                acc.x += h.x; acc.y += h.y; acc.z += h.z; acc.w += h.w;
            }
        }
    }
    #pragma unroll
    for (int off = 4; off < 32; off <<= 1) {
        acc.x += __shfl_xor_sync(0xffffffffu, acc.x, off);
        acc.y += __shfl_xor_sync(0xffffffffu, acc.y, off);
        acc.z += __shfl_xor_sync(0xffffffffu, acc.z, off);
        acc.w += __shfl_xor_sync(0xffffffffu, acc.w, off);
    }
    // lanes 0..3 hold agg1 quads; broadcast all 16 values to every lane
    float di = g_dinv[i];
    float v16[16];
    #pragma unroll
    for (int j = 0; j < 4; j++) {
        v16[j * 4 + 0] = __shfl_sync(0xffffffffu, acc.x, j);
        v16[j * 4 + 1] = __shfl_sync(0xffffffffu, acc.y, j);
        v16[j * 4 + 2] = __shfl_sync(0xffffffffu, acc.z, j);
        v16[j * 4 + 3] = __shfl_sync(0xffffffffu, acc.w, j);
    }
    #pragma unroll
    for (int f = 0; f < 16; f++)
        v16[f] = fmaxf(v16[f] * di + sb[f], 0.0f);
    if (lane < 8) {
        float o = 0.0f;
        if (lane < 6) {
            #pragma unroll
            for (int f = 0; f < 16; f++) o = fmaf(v16[f], sW[f * 6 + lane], o);
            o *= di;
        }
        g_h2[i * 8 + lane] = o;
    }
}

// gather layer 2 + fused bias + log_softmax -> out.
// warp per dst node; 32 csr entries per outer iter, 2 rounds (16 edges each).
__global__ void k_gather2(const float* __restrict__ b2, float* __restrict__ out) {
    int i = blockIdx.x * 8 + (threadIdx.x >> 5);
    int lane = threadIdx.x & 31;
    int g = lane >> 1;   // edge sub-slot 0..15
    int q = lane & 1;    // feature half 0..1
    int start = g_rowstart[i];
    int n = g_cnt[i];

    float4 acc;
    {   // self-loop once per half
        acc = (g == 0) ? ((const float4*)&g_h2[i * 8])[q]
                       : make_float4(0.f, 0.f, 0.f, 0.f);
    }
    for (int base = 0; base < n; base += 32) {
        int slot = base + lane;
        int v = (slot < n) ? g_csr[start + slot] : -1;
        #pragma unroll
        for (int r = 0; r < 2; r++) {
            int s = __shfl_sync(0xffffffffu, v, r * 16 + g);
            if (s >= 0) {
                float4 h = *(const float4*)&g_h2[s * 8 + q * 4];
                acc.x += h.x; acc.y += h.y; acc.z += h.z; acc.w += h.w;
            }
        }
    }
    #pragma unroll
    for (int off = 2; off < 32; off <<= 1) {
        acc.x += __shfl_xor_sync(0xffffffffu, acc.x, off);
        acc.y += __shfl_xor_sync(0xffffffffu, acc.y, off);
        acc.z += __shfl_xor_sync(0xffffffffu, acc.z, off);
        acc.w += __shfl_xor_sync(0xffffffffu, acc.w, off);
    }
    // lanes 0,1 hold the two agg2 halves; broadcast to all lanes
    float di = g_dinv[i];
    float a[8];
    a[0] = __shfl_sync(0xffffffffu, acc.x, 0);
    a[1] = __shfl_sync(0xffffffffu, acc.y, 0);
    a[2] = __shfl_sync(0xffffffffu, acc.z, 0);
    a[3] = __shfl_sync(0xffffffffu, acc.w, 0);
    a[4] = __shfl_sync(0xffffffffu, acc.x, 1);
    a[5] = __shfl_sync(0xffffffffu, acc.y, 1);
    a[6] = __shfl_sync(0xffffffffu, acc.z, 1);
    a[7] = __shfl_sync(0xffffffffu, acc.w, 1);
    float v[6];
    #pragma unroll
    for (int j = 0; j < 6; j++) v[j] = a[j] * di + __ldg(&b2[j]);
    float m = v[0];
    #pragma unroll
    for (int j = 1; j < 6; j++) m = fmaxf(m, v[j]);
    float s = 0.0f;
    #pragma unroll
    for (int j = 0; j < 6; j++) s += expf(v[j] - m);
    float l = m + logf(s);
    if (lane < 6) out[i * 6 + lane] = v[lane] - l;
}

extern "C" void kernel_launch(void* const* d_in, const int* in_sizes, int n_in,
                              void* d_out, int out_size) {
    const float* x  = (const float*)d_in[0];
    const void*  ei = d_in[1];
    const float* W1 = (const float*)d_in[2];
    const float* b1 = (const float*)d_in[3];
    const float* W2 = (const float*)d_in[4];
    const float* b2 = (const float*)d_in[5];
    float* out = (float*)d_out;

    const int T = 256;
    k_init<<<(NN + T - 1) / T, T>>>((const unsigned int*)ei);
    k_convert_count<<<(NE + T - 1) / T, T>>>(ei);
    k_scanA<<<NBLK, SCAN_B>>>();
    k_scanB<<<1, SCAN_B>>>();
    k_scanC<<<(NN + T - 1) / T, T>>>();
    k_layer1_node<<<(NN + 255) / 256, 256>>>(x, W1);
    k_fill<<<(NE + T - 1) / T, T>>>();
    k_gather1<<<NN / 8, 256>>>(b1, W2);
    k_gather2<<<NN / 8, 256>>>(b2, out);
}

// round 5
// speedup vs baseline: 1.0363x; 1.0363x over previous
#include <cuda_runtime.h>

#define NN 200000
#define NE 6400000
#define SCAN_B 512
#define NBLK ((NN + SCAN_B - 1) / SCAN_B)   // 391

// ---- scratch (device globals; no allocations allowed) ----
__device__ int   g_cnt[NN];        // in-degree (excl self-loop)
__device__ int   g_rowstart[NN];
__device__ int   g_cursor[NN];
__device__ int   g_bsum[NBLK];
__device__ int   g_boff[NBLK];
__device__ int   g_ticket;
__device__ int   g_src32[NE];
__device__ int   g_dst32[NE];
__device__ int   g_csr[NE];        // src ids grouped by dst
__device__ float g_dinv[NN];
__device__ float g_h1[NN * 16];    // h1 * dinv[i]
__device__ float g_agg1[NN * 16];
__device__ float g_h2[NN * 8];     // h2 * dinv[i], padded to 8
__device__ int   g_is64;

// ---- fused: zero counts + ticket + dtype detection ----
__global__ void k_init(const unsigned int* w) {
    int i = blockIdx.x * blockDim.x + threadIdx.x;
    if (i < NN) g_cnt[i] = 0;
    if (i == 0) {
        g_ticket = 0;
        int is64 = 1;
        #pragma unroll
        for (int k = 1; k < 32; k += 2)
            if (w[k] != 0u) is64 = 0;
        g_is64 = is64;
    }
}

// convert edge index to int32 + in-degree histogram (int atomics)
__global__ void k_convert_count(const void* __restrict__ ei) {
    int e = blockIdx.x * blockDim.x + threadIdx.x;
    if (e >= NE) return;
    int s, d;
    if (g_is64) {
        const long long* p = (const long long*)ei;
        s = (int)p[e];
        d = (int)p[(long long)NE + e];
    } else {
        const int* p = (const int*)ei;
        s = p[e];
        d = p[NE + e];
    }
    g_src32[e] = s;
    g_dst32[e] = d;
    atomicAdd(&g_cnt[d], 1);
}

// ---- prefix sum: per-block scan, last block scans the block sums ----
__global__ void k_scanA() {
    __shared__ int sh[SCAN_B];
    __shared__ int isLast;
    int i = blockIdx.x * SCAN_B + threadIdx.x;
    int v = (i < NN) ? g_cnt[i] : 0;
    sh[threadIdx.x] = v;
    __syncthreads();
    for (int off = 1; off < SCAN_B; off <<= 1) {
        int t = (threadIdx.x >= off) ? sh[threadIdx.x - off] : 0;
        __syncthreads();
        sh[threadIdx.x] += t;
        __syncthreads();
    }
    if (i < NN) g_rowstart[i] = sh[threadIdx.x] - v;   // within-block exclusive
    if (threadIdx.x == SCAN_B - 1) g_bsum[blockIdx.x] = sh[threadIdx.x];
    // last block to finish scans g_bsum -> g_boff
    __threadfence();
    if (threadIdx.x == 0)
        isLast = (atomicAdd(&g_ticket, 1) == gridDim.x - 1);
    __syncthreads();
    if (isLast) {
        int b = (threadIdx.x < NBLK) ? g_bsum[threadIdx.x] : 0;
        sh[threadIdx.x] = b;
        __syncthreads();
        for (int off = 1; off < SCAN_B; off <<= 1) {
            int t = (threadIdx.x >= off) ? sh[threadIdx.x - off] : 0;
            __syncthreads();
            sh[threadIdx.x] += t;
            __syncthreads();
        }
        if (threadIdx.x < NBLK) g_boff[threadIdx.x] = sh[threadIdx.x] - b;
    }
}

__global__ void k_scanC() {
    int i = blockIdx.x * blockDim.x + threadIdx.x;
    if (i >= NN) return;
    int r = g_rowstart[i] + g_boff[i / SCAN_B];
    g_rowstart[i] = r;
    g_cursor[i]   = r;
}

// counting-sort fill: csr[pos++] = src, grouped by dst
__global__ void k_fill() {
    int e = blockIdx.x * blockDim.x + threadIdx.x;
    if (e >= NE) return;
    int d = g_dst32[e];
    int pos = atomicAdd(&g_cursor[d], 1);
    g_csr[pos] = g_src32[e];
}

// dinv + layer-1 GEMM (x[21] @ W1[21x16]), x tiled through smem, pre-scaled by dinv
__global__ void k_layer1_node(const float* __restrict__ x, const float* __restrict__ W1) {
    __shared__ float sW[21 * 16];
    __shared__ float sX[256 * 21];
    for (int t = threadIdx.x; t < 21 * 16; t += blockDim.x) sW[t] = W1[t];
    int base = blockIdx.x * 256;
    {
        long long gbase = (long long)base * 21;
        int lim = (NN - base) * 21;
        if (lim > 256 * 21) lim = 256 * 21;
        for (int t = threadIdx.x; t < lim; t += blockDim.x)
            sX[t] = x[gbase + t];
    }
    __syncthreads();
    int i = base + threadIdx.x;
    if (i >= NN) return;
    float di = rsqrtf((float)g_cnt[i] + 1.0f);   // +1 self-loop
    g_dinv[i] = di;
    const float* xi = &sX[threadIdx.x * 21];
    float acc[16];
    #pragma unroll
    for (int f = 0; f < 16; f++) acc[f] = 0.0f;
    #pragma unroll
    for (int k = 0; k < 21; k++) {
        float xk = xi[k];
        #pragma unroll
        for (int f = 0; f < 16; f++) acc[f] = fmaf(xk, sW[k * 16 + f], acc[f]);
    }
    float4* h1p = (float4*)&g_h1[i * 16];
    #pragma unroll
    for (int q = 0; q < 4; q++) {
        float4 v;
        v.x = acc[q * 4 + 0] * di;
        v.y = acc[q * 4 + 1] * di;
        v.z = acc[q * 4 + 2] * di;
        v.w = acc[q * 4 + 3] * di;
        h1p[q] = v;
    }
}

// gather layer 1: warp per dst node; 32 csr entries per outer iter (coalesced),
// 4 shfl rounds of 8 edges each; 4 lanes per edge; register accumulate.
__global__ void k_gather1() {
    int i = blockIdx.x * 8 + (threadIdx.x >> 5);
    int lane = threadIdx.x & 31;
    int g = lane >> 2;   // edge sub-slot 0..7
    int q = lane & 3;    // feature quad 0..3
    int start = g_rowstart[i];
    int n = g_cnt[i];
    float4 acc = make_float4(0.f, 0.f, 0.f, 0.f);
    for (int base = 0; base < n; base += 32) {
        int slot = base + lane;
        int v = (slot < n) ? g_csr[start + slot] : -1;
        #pragma unroll
        for (int r = 0; r < 4; r++) {
            int s = __shfl_sync(0xffffffffu, v, r * 8 + g);
            if (s >= 0) {
                float4 h = *(const float4*)&g_h1[s * 16 + q * 4];
                acc.x += h.x; acc.y += h.y; acc.z += h.z; acc.w += h.w;
            }
        }
    }
    #pragma unroll
    for (int off = 4; off < 32; off <<= 1) {
        acc.x += __shfl_xor_sync(0xffffffffu, acc.x, off);
        acc.y += __shfl_xor_sync(0xffffffffu, acc.y, off);
        acc.z += __shfl_xor_sync(0xffffffffu, acc.z, off);
        acc.w += __shfl_xor_sync(0xffffffffu, acc.w, off);
    }
    if (lane < 4) {   // lane == q
        float4 h = ((const float4*)&g_h1[i * 16])[lane];  // self-loop
        acc.x += h.x; acc.y += h.y; acc.z += h.z; acc.w += h.w;
        ((float4*)&g_agg1[i * 16])[lane] = acc;
    }
}

// relu(agg1*dinv + b1) @ W2[16x6], pre-scale, padded to 8
__global__ void k_layer2_node(const float* __restrict__ b1, const float* __restrict__ W2) {
    __shared__ float sW[16 * 6];
    __shared__ float sb[16];
    for (int t = threadIdx.x; t < 96; t += blockDim.x) sW[t] = W2[t];
    if (threadIdx.x < 16) sb[threadIdx.x] = b1[threadIdx.x];
    __syncthreads();
    int i = blockIdx.x * blockDim.x + threadIdx.x;
    if (i >= NN) return;
    float di = g_dinv[i];
    float v[16];
    const float4* a1p = (const float4*)&g_agg1[i * 16];
    #pragma unroll
    for (int qq = 0; qq < 4; qq++) {
        float4 a = a1p[qq];
        v[qq * 4 + 0] = fmaxf(a.x * di + sb[qq * 4 + 0], 0.0f);
        v[qq * 4 + 1] = fmaxf(a.y * di + sb[qq * 4 + 1], 0.0f);
        v[qq * 4 + 2] = fmaxf(a.z * di + sb[qq * 4 + 2], 0.0f);
        v[qq * 4 + 3] = fmaxf(a.w * di + sb[qq * 4 + 3], 0.0f);
    }
    float o[6];
    #pragma unroll
    for (int j = 0; j < 6; j++) {
        float s = 0.0f;
        #pragma unroll
        for (int f = 0; f < 16; f++) s = fmaf(v[f], sW[f * 6 + j], s);
        o[j] = s * di;
    }
    *(float4*)&g_h2[i * 8]     = make_float4(o[0], o[1], o[2], o[3]);
    *(float4*)&g_h2[i * 8 + 4] = make_float4(o[4], o[5], 0.0f, 0.0f);
}

// gather layer 2 + fused bias + log_softmax -> out.
// warp per dst node; 32 csr entries per outer iter, 2 shfl rounds of 16 edges.
__global__ void k_gather2(const float* __restrict__ b2, float* __restrict__ out) {
    int i = blockIdx.x * 8 + (threadIdx.x >> 5);
    int lane = threadIdx.x & 31;
    int g = lane >> 1;   // edge sub-slot 0..15
    int q = lane & 1;    // feature half 0..1
    int start = g_rowstart[i];
    int n = g_cnt[i];
    float4 acc = (g == 0) ? ((const float4*)&g_h2[i * 8])[q]   // self-loop
                          : make_float4(0.f, 0.f, 0.f, 0.f);
    for (int base = 0; base < n; base += 32) {
        int slot = base + lane;
        int v = (slot < n) ? g_csr[start + slot] : -1;
        #pragma unroll
        for (int r = 0; r < 2; r++) {
            int s = __shfl_sync(0xffffffffu, v, r * 16 + g);
            if (s >= 0) {
                float4 h = *(const float4*)&g_h2[s * 8 + q * 4];
                acc.x += h.x; acc.y += h.y; acc.z += h.z; acc.w += h.w;
            }
        }
    }
    #pragma unroll
    for (int off = 2; off < 32; off <<= 1) {
        acc.x += __shfl_xor_sync(0xffffffffu, acc.x, off);
        acc.y += __shfl_xor_sync(0xffffffffu, acc.y, off);
        acc.z += __shfl_xor_sync(0xffffffffu, acc.z, off);
        acc.w += __shfl_xor_sync(0xffffffffu, acc.w, off);
    }
    // lanes 0,1 hold the two agg2 halves; broadcast to all lanes
    float di = g_dinv[i];
    float a[8];
    a[0] = __shfl_sync(0xffffffffu, acc.x, 0);
    a[1] = __shfl_sync(0xffffffffu, acc.y, 0);
    a[2] = __shfl_sync(0xffffffffu, acc.z, 0);
    a[3] = __shfl_sync(0xffffffffu, acc.w, 0);
    a[4] = __shfl_sync(0xffffffffu, acc.x, 1);
    a[5] = __shfl_sync(0xffffffffu, acc.y, 1);
    a[6] = __shfl_sync(0xffffffffu, acc.z, 1);
    a[7] = __shfl_sync(0xffffffffu, acc.w, 1);
    float v[6];
    #pragma unroll
    for (int j = 0; j < 6; j++) v[j] = a[j] * di + __ldg(&b2[j]);
    float m = v[0];
    #pragma unroll
    for (int j = 1; j < 6; j++) m = fmaxf(m, v[j]);
    float s = 0.0f;
    #pragma unroll
    for (int j = 0; j < 6; j++) s += expf(v[j] - m);
    float l = m + logf(s);
    if (lane < 6) out[i * 6 + lane] = v[lane] - l;
}

extern "C" void kernel_launch(void* const* d_in, const int* in_sizes, int n_in,
                              void* d_out, int out_size) {
    const float* x  = (const float*)d_in[0];
    const void*  ei = d_in[1];
    const float* W1 = (const float*)d_in[2];
    const float* b1 = (const float*)d_in[3];
    const float* W2 = (const float*)d_in[4];
    const float* b2 = (const float*)d_in[5];
    float* out = (float*)d_out;

    const int T = 256;
    k_init<<<(NN + T - 1) / T, T>>>((const unsigned int*)ei);
    k_convert_count<<<(NE + T - 1) / T, T>>>(ei);
    k_scanA<<<NBLK, SCAN_B>>>();
    k_scanC<<<(NN + T - 1) / T, T>>>();
    k_layer1_node<<<(NN + 255) / 256, 256>>>(x, W1);
    k_fill<<<(NE + T - 1) / T, T>>>();
    k_gather1<<<NN / 8, 256>>>();
    k_layer2_node<<<(NN + T - 1) / T, T>>>(b1, W2);
    k_gather2<<<NN / 8, 256>>>(b2, out);
}

// round 6
// speedup vs baseline: 1.0379x; 1.0016x over previous
#include <cuda_runtime.h>
#include <cuda_fp16.h>

#define NN 200000
#define NE 6400000
#define SCAN_B 512
#define NBLK ((NN + SCAN_B - 1) / SCAN_B)   // 391

// ---- scratch (device globals; no allocations allowed) ----
__device__ int   g_cnt[NN];        // in-degree (excl self-loop)
__device__ int   g_rowstart[NN];
__device__ int   g_cursor[NN];
__device__ int   g_bsum[NBLK];
__device__ int   g_boff[NBLK];
__device__ int   g_ticket;
__device__ int   g_src32[NE];
__device__ int   g_dst32[NE];
__device__ int   g_csr[NE];        // src ids grouped by dst
__device__ float g_dinv[NN];
__device__ uint4 g_h1h[NN * 2];    // h1 * dinv[i], fp16: 16 halfs = 2 uint4 per row
__device__ float g_agg1[NN * 16];
__device__ float g_h2[NN * 8];     // h2 * dinv[i], fp32, padded to 8
__device__ int   g_is64;

// ---- fused: zero counts + ticket + dtype detection ----
__global__ void k_init(const unsigned int* w) {
    int i = blockIdx.x * blockDim.x + threadIdx.x;
    if (i < NN) g_cnt[i] = 0;
    if (i == 0) {
        g_ticket = 0;
        int is64 = 1;
        #pragma unroll
        for (int k = 1; k < 32; k += 2)
            if (w[k] != 0u) is64 = 0;
        g_is64 = is64;
    }
}

// convert edge index to int32 + in-degree histogram (int atomics)
__global__ void k_convert_count(const void* __restrict__ ei) {
    int e = blockIdx.x * blockDim.x + threadIdx.x;
    if (e >= NE) return;
    int s, d;
    if (g_is64) {
        const long long* p = (const long long*)ei;
        s = (int)p[e];
        d = (int)p[(long long)NE + e];
    } else {
        const int* p = (const int*)ei;
        s = p[e];
        d = p[NE + e];
    }
    g_src32[e] = s;
    g_dst32[e] = d;
    atomicAdd(&g_cnt[d], 1);
}

// ---- prefix sum: per-block scan, last block scans the block sums ----
__global__ void k_scanA() {
    __shared__ int sh[SCAN_B];
    __shared__ int isLast;
    int i = blockIdx.x * SCAN_B + threadIdx.x;
    int v = (i < NN) ? g_cnt[i] : 0;
    sh[threadIdx.x] = v;
    __syncthreads();
    for (int off = 1; off < SCAN_B; off <<= 1) {
        int t = (threadIdx.x >= off) ? sh[threadIdx.x - off] : 0;
        __syncthreads();
        sh[threadIdx.x] += t;
        __syncthreads();
    }
    if (i < NN) g_rowstart[i] = sh[threadIdx.x] - v;   // within-block exclusive
    if (threadIdx.x == SCAN_B - 1) g_bsum[blockIdx.x] = sh[threadIdx.x];
    __threadfence();
    if (threadIdx.x == 0)
        isLast = (atomicAdd(&g_ticket, 1) == gridDim.x - 1);
    __syncthreads();
    if (isLast) {
        int b = (threadIdx.x < NBLK) ? g_bsum[threadIdx.x] : 0;
        sh[threadIdx.x] = b;
        __syncthreads();
        for (int off = 1; off < SCAN_B; off <<= 1) {
            int t = (threadIdx.x >= off) ? sh[threadIdx.x - off] : 0;
            __syncthreads();
            sh[threadIdx.x] += t;
            __syncthreads();
        }
        if (threadIdx.x < NBLK) g_boff[threadIdx.x] = sh[threadIdx.x] - b;
    }
}

__global__ void k_scanC() {
    int i = blockIdx.x * blockDim.x + threadIdx.x;
    if (i >= NN) return;
    int r = g_rowstart[i] + g_boff[i / SCAN_B];
    g_rowstart[i] = r;
    g_cursor[i]   = r;
}

// counting-sort fill: csr[pos++] = src, grouped by dst
__global__ void k_fill() {
    int e = blockIdx.x * blockDim.x + threadIdx.x;
    if (e >= NE) return;
    int d = g_dst32[e];
    int pos = atomicAdd(&g_cursor[d], 1);
    g_csr[pos] = g_src32[e];
}

// dinv + layer-1 GEMM (x[21] @ W1[21x16]), pre-scaled by dinv, stored fp16
__global__ void k_layer1_node(const float* __restrict__ x, const float* __restrict__ W1) {
    __shared__ float sW[21 * 16];
    __shared__ float sX[256 * 21];
    for (int t = threadIdx.x; t < 21 * 16; t += blockDim.x) sW[t] = W1[t];
    int base = blockIdx.x * 256;
    {
        long long gbase = (long long)base * 21;
        int lim = (NN - base) * 21;
        if (lim > 256 * 21) lim = 256 * 21;
        for (int t = threadIdx.x; t < lim; t += blockDim.x)
            sX[t] = x[gbase + t];
    }
    __syncthreads();
    int i = base + threadIdx.x;
    if (i >= NN) return;
    float di = rsqrtf((float)g_cnt[i] + 1.0f);   // +1 self-loop
    g_dinv[i] = di;
    const float* xi = &sX[threadIdx.x * 21];
    float acc[16];
    #pragma unroll
    for (int f = 0; f < 16; f++) acc[f] = 0.0f;
    #pragma unroll
    for (int k = 0; k < 21; k++) {
        float xk = xi[k];
        #pragma unroll
        for (int f = 0; f < 16; f++) acc[f] = fmaf(xk, sW[k * 16 + f], acc[f]);
    }
    #pragma unroll
    for (int h = 0; h < 2; h++) {
        uint4 raw;
        __half2* o = (__half2*)&raw;
        #pragma unroll
        for (int k = 0; k < 4; k++)
            o[k] = __floats2half2_rn(acc[h * 8 + 2 * k] * di, acc[h * 8 + 2 * k + 1] * di);
        g_h1h[i * 2 + h] = raw;
    }
}

// gather layer 1 (fp16 rows, 32B): warp per dst node; 2 lanes per edge,
// 16 edges per iter; fp32 register accumulate.
__global__ void k_gather1() {
    int i = blockIdx.x * 8 + (threadIdx.x >> 5);
    int lane = threadIdx.x & 31;
    int g = lane >> 1;   // edge slot 0..15
    int q = lane & 1;    // 8-half chunk 0..1
    int start = g_rowstart[i];
    int n = g_cnt[i];
    float acc[8];
    #pragma unroll
    for (int k = 0; k < 8; k++) acc[k] = 0.0f;
    for (int base = 0; base < n; base += 16) {
        int slot = base + lane;
        int v = (lane < 16 && slot < n) ? g_csr[start + slot] : -1;
        int s = __shfl_sync(0xffffffffu, v, g);
        if (s >= 0) {
            uint4 raw = g_h1h[s * 2 + q];
            const __half2* hp = (const __half2*)&raw;
            #pragma unroll
            for (int k = 0; k < 4; k++) {
                float2 f = __half22float2(hp[k]);
                acc[2 * k]     += f.x;
                acc[2 * k + 1] += f.y;
            }
        }
    }
    #pragma unroll
    for (int off = 2; off < 32; off <<= 1) {
        #pragma unroll
        for (int k = 0; k < 8; k++)
            acc[k] += __shfl_xor_sync(0xffffffffu, acc[k], off);
    }
    if (lane < 2) {   // lane == q
        uint4 raw = g_h1h[i * 2 + lane];   // self-loop
        const __half2* hp = (const __half2*)&raw;
        #pragma unroll
        for (int k = 0; k < 4; k++) {
            float2 f = __half22float2(hp[k]);
            acc[2 * k]     += f.x;
            acc[2 * k + 1] += f.y;
        }
        float4* ap = (float4*)&g_agg1[i * 16 + lane * 8];
        ap[0] = make_float4(acc[0], acc[1], acc[2], acc[3]);
        ap[1] = make_float4(acc[4], acc[5], acc[6], acc[7]);
    }
}

// relu(agg1*dinv + b1) @ W2[16x6], pre-scale, fp32 padded to 8
__global__ void k_layer2_node(const float* __restrict__ b1, const float* __restrict__ W2) {
    __shared__ float sW[16 * 6];
    __shared__ float sb[16];
    for (int t = threadIdx.x; t < 96; t += blockDim.x) sW[t] = W2[t];
    if (threadIdx.x < 16) sb[threadIdx.x] = b1[threadIdx.x];
    __syncthreads();
    int i = blockIdx.x * blockDim.x + threadIdx.x;
    if (i >= NN) return;
    float di = g_dinv[i];
    float v[16];
    const float4* a1p = (const float4*)&g_agg1[i * 16];
    #pragma unroll
    for (int qq = 0; qq < 4; qq++) {
        float4 a = a1p[qq];
        v[qq * 4 + 0] = fmaxf(a.x * di + sb[qq * 4 + 0], 0.0f);
        v[qq * 4 + 1] = fmaxf(a.y * di + sb[qq * 4 + 1], 0.0f);
        v[qq * 4 + 2] = fmaxf(a.z * di + sb[qq * 4 + 2], 0.0f);
        v[qq * 4 + 3] = fmaxf(a.w * di + sb[qq * 4 + 3], 0.0f);
    }
    float o[6];
    #pragma unroll
    for (int j = 0; j < 6; j++) {
        float s = 0.0f;
        #pragma unroll
        for (int f = 0; f < 16; f++) s = fmaf(v[f], sW[f * 6 + j], s);
        o[j] = s * di;
    }
    *(float4*)&g_h2[i * 8]     = make_float4(o[0], o[1], o[2], o[3]);
    *(float4*)&g_h2[i * 8 + 4] = make_float4(o[4], o[5], 0.0f, 0.0f);
}

// gather layer 2 + fused bias + log_softmax -> out (R3 loop shape).
__global__ void k_gather2(const float* __restrict__ b2, float* __restrict__ out) {
    int i = blockIdx.x * 8 + (threadIdx.x >> 5);
    int lane = threadIdx.x & 31;
    int g = lane >> 1;   // edge slot 0..15
    int q = lane & 1;    // feature half 0..1
    int start = g_rowstart[i];
    int n = g_cnt[i];
    float4 acc = (g == 0) ? ((const float4*)&g_h2[i * 8])[q]   // self-loop
                          : make_float4(0.f, 0.f, 0.f, 0.f);
    for (int base = 0; base < n; base += 16) {
        int slot = base + lane;
        int v = (lane < 16 && slot < n) ? g_csr[start + slot] : -1;
        int s = __shfl_sync(0xffffffffu, v, g);
        if (s >= 0) {
            float4 h = *(const float4*)&g_h2[s * 8 + q * 4];
            acc.x += h.x; acc.y += h.y; acc.z += h.z; acc.w += h.w;
        }
    }
    #pragma unroll
    for (int off = 2; off < 32; off <<= 1) {
        acc.x += __shfl_xor_sync(0xffffffffu, acc.x, off);
        acc.y += __shfl_xor_sync(0xffffffffu, acc.y, off);
        acc.z += __shfl_xor_sync(0xffffffffu, acc.z, off);
        acc.w += __shfl_xor_sync(0xffffffffu, acc.w, off);
    }
    float di = g_dinv[i];
    float a[8];
    a[0] = __shfl_sync(0xffffffffu, acc.x, 0);
    a[1] = __shfl_sync(0xffffffffu, acc.y, 0);
    a[2] = __shfl_sync(0xffffffffu, acc.z, 0);
    a[3] = __shfl_sync(0xffffffffu, acc.w, 0);
    a[4] = __shfl_sync(0xffffffffu, acc.x, 1);
    a[5] = __shfl_sync(0xffffffffu, acc.y, 1);
    a[6] = __shfl_sync(0xffffffffu, acc.z, 1);
    a[7] = __shfl_sync(0xffffffffu, acc.w, 1);
    float v[6];
    #pragma unroll
    for (int j = 0; j < 6; j++) v[j] = a[j] * di + __ldg(&b2[j]);
    float m = v[0];
    #pragma unroll
    for (int j = 1; j < 6; j++) m = fmaxf(m, v[j]);
    float s = 0.0f;
    #pragma unroll
    for (int j = 0; j < 6; j++) s += expf(v[j] - m);
    float l = m + logf(s);
    if (lane < 6) out[i * 6 + lane] = v[lane] - l;
}

extern "C" void kernel_launch(void* const* d_in, const int* in_sizes, int n_in,
                              void* d_out, int out_size) {
    const float* x  = (const float*)d_in[0];
    const void*  ei = d_in[1];
    const float* W1 = (const float*)d_in[2];
    const float* b1 = (const float*)d_in[3];
    const float* W2 = (const float*)d_in[4];
    const float* b2 = (const float*)d_in[5];
    float* out = (float*)d_out;

    const int T = 256;
    k_init<<<(NN + T - 1) / T, T>>>((const unsigned int*)ei);
    k_convert_count<<<(NE + T - 1) / T, T>>>(ei);
    k_scanA<<<NBLK, SCAN_B>>>();
    k_scanC<<<(NN + T - 1) / T, T>>>();
    k_layer1_node<<<(NN + 255) / 256, 256>>>(x, W1);
    k_fill<<<(NE + T - 1) / T, T>>>();
    k_gather1<<<NN / 8, 256>>>();
    k_layer2_node<<<(NN + T - 1) / T, T>>>(b1, W2);
    k_gather2<<<NN / 8, 256>>>(b2, out);
}